// round 11
// baseline (speedup 1.0000x reference)
#include <cuda_runtime.h>
#include <math.h>

// Problem constants
#define HIDDEN   128
#define NPTS     1024
#define NPAIRS   (NPTS * NPTS)          // 1,048,576
#define G_TAB    128                    // lookup-table rows over a in [0, 12]
#define PPB      16                     // pairs per block
#define PI_F     3.14159265358979323846f

// 64 KB lookup table: T[g][h] = f_h(a_g), a_g = g * 12/(G_TAB-1).
static __device__ float g_table[G_TAB * HIDDEN];
// Build-completion counter; reset to 0 by a memset node each launch.
static __device__ int   g_done;

// ---------------------------------------------------------------------------
// Fused kernel.
//   Blocks 0..G_TAB-1 additionally build one table row each (warp-cooperative
//   dot, coalesced W reads), then signal via g_done.  All blocks: phase 1
//   (table-independent atan2 prep, overlaps with the build), wait for
//   g_done==G_TAB, then phase 2 (lerp + streaming stores).
// ---------------------------------------------------------------------------
__global__ __launch_bounds__(HIDDEN) void fused_geom_embed_kernel(
    const float* __restrict__ normals,  // [1024][3]
    const float* __restrict__ W,        // [128][128] row-major
    const float* __restrict__ b,        // [128]
    float*       __restrict__ out)      // [1024*1024][128]
{
    __shared__ float emb[HIDDEN];
    __shared__ int   s_g[PPB];
    __shared__ float s_f[PPB];

    const int  tid   = threadIdx.x;
    const int  warp  = tid >> 5;
    const int  lane  = tid & 31;
    const int  bid   = blockIdx.x;
    const long pbase = (long)bid * PPB;

    // ---- Builder role: blocks 0..G_TAB-1 build table row g = bid ----------
    if (bid < G_TAB) {
        const float a = (float)bid * (12.0f / (float)(G_TAB - 1));

        if (tid < HIDDEN / 2) {
            // div_term[k] = exp(-k * ln(10000)/64), k = tid
            const float w     = expf(-(float)tid * (9.210340371976184f / 64.0f));
            const float omega = a * w;
            float s, c;
            sincosf(omega, &s, &c);
            emb[2 * tid]     = s;
            emb[2 * tid + 1] = c;
        }
        __syncthreads();

        const float4 e = ((const float4*)emb)[lane];
        const float4* __restrict__ W4 = (const float4*)W;   // 32 float4 per row

#pragma unroll
        for (int k = 0; k < 32; ++k) {
            const int c = warp * 32 + k;
            const float4 wv = W4[c * 32 + lane];

            float s = e.x * wv.x;
            s = fmaf(e.y, wv.y, s);
            s = fmaf(e.z, wv.z, s);
            s = fmaf(e.w, wv.w, s);

#pragma unroll
            for (int off = 16; off > 0; off >>= 1)
                s += __shfl_xor_sync(0xFFFFFFFFu, s, off);

            if (lane == 0)
                g_table[bid * HIDDEN + c] = s + b[c];
        }

        __syncthreads();
        __threadfence();                 // table row visible before signal
        if (tid == 0)
            atomicAdd(&g_done, 1);
    }

    // ---- Phase 1: per-pair (gi, frac); independent of the table -----------
    if (tid < PPB) {
        const int p = (int)pbase + tid;
        const int i = p >> 10;
        const int j = p & (NPTS - 1);

        const float ax = normals[i * 3 + 0];
        const float ay = normals[i * 3 + 1];
        const float az = normals[i * 3 + 2];
        const float bx = normals[j * 3 + 0];
        const float by = normals[j * 3 + 1];
        const float bz = normals[j * 3 + 2];

        const float cx = ay * bz - az * by;
        const float cy = az * bx - ax * bz;
        const float cz = ax * by - ay * bx;

        const float sv  = sqrtf(cx * cx + cy * cy + cz * cz);
        const float cv  = ax * bx + ay * by + az * bz;
        const float ang = atan2f(sv, cv);            // in [0, pi]

        float u = ang * ((float)(G_TAB - 1) / PI_F);
        u = fminf(fmaxf(u, 0.0f), (float)(G_TAB - 1));
        int gi = (int)u;
        if (gi > G_TAB - 2) gi = G_TAB - 2;
        s_g[tid] = gi;
        s_f[tid] = u - (float)gi;
    }
    __syncthreads();

    // ---- Wait for the full table (fast path: single load) -----------------
    if (tid == 0) {
        if (*(volatile int*)&g_done < G_TAB) {
            while (*(volatile int*)&g_done < G_TAB)
                __nanosleep(200);
        }
        __threadfence();                 // acquire: order table loads after flag
    }
    __syncthreads();

    // ---- Phase 2: lerp table rows, streaming stores ------------------------
    const float4* __restrict__ T4 = (const float4*)g_table;   // 32 float4/row
    float4* __restrict__ out4     = (float4*)out;

#pragma unroll
    for (int it = 0; it < PPB / 4; ++it) {
        const int   pl = warp + it * 4;       // pair handled by this warp
        const int   gi = s_g[pl];
        const float f  = s_f[pl];

        const float4 c0 = T4[gi * 32 + lane];
        const float4 c1 = T4[gi * 32 + 32 + lane];

        float4 r;
        r.x = fmaf(f, c1.x - c0.x, c0.x);
        r.y = fmaf(f, c1.y - c0.y, c0.y);
        r.z = fmaf(f, c1.z - c0.z, c0.z);
        r.w = fmaf(f, c1.w - c0.w, c0.w);

        // Streaming store: output is never re-read.
        __stcs(&out4[(pbase + pl) * 32 + lane], r);
    }
}

// ---------------------------------------------------------------------------
// Launch.  Inputs (metadata order): points[unused], normals, W, b.
// One memset node (reset g_done) + one fused kernel node.
// ---------------------------------------------------------------------------
extern "C" void kernel_launch(void* const* d_in, const int* in_sizes, int n_in,
                              void* d_out, int out_size)
{
    const float* normals = (const float*)d_in[1];
    const float* W       = (const float*)d_in[2];
    const float* b       = (const float*)d_in[3];
    float* out           = (float*)d_out;

    void* dflag = nullptr;
    cudaGetSymbolAddress(&dflag, g_done);
    cudaMemsetAsync(dflag, 0, sizeof(int), 0);

    fused_geom_embed_kernel<<<NPAIRS / PPB, HIDDEN>>>(normals, W, b, out);
}

// round 13
// speedup vs baseline: 1.5106x; 1.5106x over previous
#include <cuda_runtime.h>
#include <math.h>

// Problem constants
#define HIDDEN   128
#define NPTS     1024
#define NPAIRS   (NPTS * NPTS)          // 1,048,576
#define G_TAB    128                    // lookup-table rows over a in [0, 12]
#define PPB      16                     // pairs per block in the main kernel
#define PI_F     3.14159265358979323846f

// 64 KB lookup table: T[g][h] = f_h(a_g), a_g = g * 12/(G_TAB-1).
// Fully L1-resident in the main kernel.
static __device__ float g_table[G_TAB * HIDDEN];

// ---------------------------------------------------------------------------
// Kernel 1: build the table.
// One block per grid row g.  64 threads build the sinusoidal embedding into
// smem; then each warp computes 32 output channels via warp-cooperative dot:
// lane l loads W[c][4l..4l+3] (coalesced 128B row segment, L1-hot), FMAs with
// emb[4l..4l+3], and a butterfly reduction produces the channel value.
// ---------------------------------------------------------------------------
__global__ __launch_bounds__(HIDDEN) void build_table_kernel(
    const float* __restrict__ W,   // [128][128] row-major
    const float* __restrict__ b)   // [128]
{
    __shared__ float emb[HIDDEN];
    const int g    = blockIdx.x;
    const int tid  = threadIdx.x;
    const int warp = tid >> 5;
    const int lane = tid & 31;

    const float a = (float)g * (12.0f / (float)(G_TAB - 1));

    if (tid < HIDDEN / 2) {
        // div_term[k] = exp(-k * ln(10000)/64), k = tid
        const float w     = expf(-(float)tid * (9.210340371976184f / 64.0f));
        const float omega = a * w;
        float s, c;
        sincosf(omega, &s, &c);
        emb[2 * tid]     = s;
        emb[2 * tid + 1] = c;
    }
    __syncthreads();

    // Lane-private embedding chunk (smem LDS.128, conflict-free)
    const float4 e = ((const float4*)emb)[lane];

    const float4* __restrict__ W4 = (const float4*)W;   // 32 float4 per row

#pragma unroll
    for (int k = 0; k < 32; ++k) {
        const int c = warp * 32 + k;                    // channel this warp computes
        const float4 wv = W4[c * 32 + lane];

        float s = e.x * wv.x;
        s = fmaf(e.y, wv.y, s);
        s = fmaf(e.z, wv.z, s);
        s = fmaf(e.w, wv.w, s);

        // Butterfly reduction across the warp
#pragma unroll
        for (int off = 16; off > 0; off >>= 1)
            s += __shfl_xor_sync(0xFFFFFFFFu, s, off);

        if (lane == 0)
            g_table[g * HIDDEN + c] = s + b[c];
    }
}

// ---------------------------------------------------------------------------
// Kernel 2: main.  Each block handles PPB=16 pairs; warp w owns pairs
// {w, w+4, w+8, w+12} (block-local).
//   Phase 1 (warp-local, no __syncthreads): lanes 0..3 compute (gi, frac)
//     for the warp's 4 pairs (1 atan2 per pair).
//   Phase 2: per iteration the warp lerps one pair's 128-float row
//     (float4 per lane): 2 x 512B table loads (L1-hot) + 512B streaming store.
//     Pair params come from __shfl_sync broadcasts — zero smem, zero barriers.
// ---------------------------------------------------------------------------
__global__ __launch_bounds__(HIDDEN) void geom_embed_kernel(
    const float* __restrict__ normals,  // [1024][3]
    float*       __restrict__ out)      // [1024*1024][128]
{
    const int  tid   = threadIdx.x;
    const int  warp  = tid >> 5;
    const int  lane  = tid & 31;
    const long pbase = (long)blockIdx.x * PPB;

    // Phase 1: lanes 0..3 each handle one of this warp's pairs.
    int   gi_r = 0;
    float f_r  = 0.0f;
    if (lane < 4) {
        const int p = (int)pbase + warp + lane * 4;
        const int i = p >> 10;
        const int j = p & (NPTS - 1);

        const float ax = normals[i * 3 + 0];
        const float ay = normals[i * 3 + 1];
        const float az = normals[i * 3 + 2];
        const float bx = normals[j * 3 + 0];
        const float by = normals[j * 3 + 1];
        const float bz = normals[j * 3 + 2];

        const float cx = ay * bz - az * by;
        const float cy = az * bx - ax * bz;
        const float cz = ax * by - ay * bx;

        const float sv  = sqrtf(cx * cx + cy * cy + cz * cz);
        const float cv  = ax * bx + ay * by + az * bz;
        const float ang = atan2f(sv, cv);            // in [0, pi]

        // u = a * (G-1)/12 = ang * (G-1)/pi
        float u = ang * ((float)(G_TAB - 1) / PI_F);
        u = fminf(fmaxf(u, 0.0f), (float)(G_TAB - 1));
        int gi = (int)u;
        if (gi > G_TAB - 2) gi = G_TAB - 2;
        gi_r = gi;
        f_r  = u - (float)gi;
    }

    const float4* __restrict__ T4 = (const float4*)g_table;   // 32 float4 per row
    float4* __restrict__ out4     = (float4*)out;

#pragma unroll
    for (int it = 0; it < PPB / 4; ++it) {
        // Broadcast pair params computed by lane `it`.
        const int   gi = __shfl_sync(0xFFFFFFFFu, gi_r, it);
        const float f  = __shfl_sync(0xFFFFFFFFu, f_r,  it);
        const int   pl = warp + it * 4;       // pair-local index for this warp

        const float4 c0 = T4[gi * 32 + lane];
        const float4 c1 = T4[gi * 32 + 32 + lane];

        float4 r;
        r.x = fmaf(f, c1.x - c0.x, c0.x);
        r.y = fmaf(f, c1.y - c0.y, c0.y);
        r.z = fmaf(f, c1.z - c0.z, c0.z);
        r.w = fmaf(f, c1.w - c0.w, c0.w);

        // Streaming store: output is never re-read.
        __stcs(&out4[(pbase + pl) * 32 + lane], r);
    }
}

// ---------------------------------------------------------------------------
// Launch.  Inputs (metadata order): points[unused], normals, W, b.
// ---------------------------------------------------------------------------
extern "C" void kernel_launch(void* const* d_in, const int* in_sizes, int n_in,
                              void* d_out, int out_size)
{
    const float* normals = (const float*)d_in[1];
    const float* W       = (const float*)d_in[2];
    const float* b       = (const float*)d_in[3];
    float* out           = (float*)d_out;

    build_table_kernel<<<G_TAB, HIDDEN>>>(W, b);
    geom_embed_kernel<<<NPAIRS / PPB, HIDDEN>>>(normals, out);
}

// round 14
// speedup vs baseline: 1.5161x; 1.0037x over previous
#include <cuda_runtime.h>
#include <math.h>

// Problem constants
#define HIDDEN   128
#define NPTS     1024
#define NPAIRS   (NPTS * NPTS)          // 1,048,576
#define G_TAB    128                    // lookup-table rows over a in [0, 12]
#define PPB      16                     // pairs per block in the main kernel
#define PI_F     3.14159265358979323846f

// 64 KB lookup table: T[g][h] = f_h(a_g), a_g = g * 12/(G_TAB-1).
// Fully L1-resident in the main kernel.
static __device__ float g_table[G_TAB * HIDDEN];

// ---------------------------------------------------------------------------
// Kernel 1: build the table.
// One block per grid row g.  64 threads build the sinusoidal embedding into
// smem; then each warp computes 32 output channels via warp-cooperative dot:
// lane l loads W[c][4l..4l+3] (coalesced 128B row segment, L1-hot), FMAs with
// emb[4l..4l+3], and a butterfly reduction produces the channel value.
// ---------------------------------------------------------------------------
__global__ __launch_bounds__(HIDDEN) void build_table_kernel(
    const float* __restrict__ W,   // [128][128] row-major
    const float* __restrict__ b)   // [128]
{
    __shared__ float emb[HIDDEN];
    const int g    = blockIdx.x;
    const int tid  = threadIdx.x;
    const int warp = tid >> 5;
    const int lane = tid & 31;

    const float a = (float)g * (12.0f / (float)(G_TAB - 1));

    if (tid < HIDDEN / 2) {
        // div_term[k] = exp(-k * ln(10000)/64), k = tid
        const float w     = expf(-(float)tid * (9.210340371976184f / 64.0f));
        const float omega = a * w;
        float s, c;
        sincosf(omega, &s, &c);
        emb[2 * tid]     = s;
        emb[2 * tid + 1] = c;
    }
    __syncthreads();

    // Lane-private embedding chunk (smem LDS.128, conflict-free)
    const float4 e = ((const float4*)emb)[lane];

    const float4* __restrict__ W4 = (const float4*)W;   // 32 float4 per row

#pragma unroll
    for (int k = 0; k < 32; ++k) {
        const int c = warp * 32 + k;                    // channel this warp computes
        const float4 wv = W4[c * 32 + lane];

        float s = e.x * wv.x;
        s = fmaf(e.y, wv.y, s);
        s = fmaf(e.z, wv.z, s);
        s = fmaf(e.w, wv.w, s);

        // Butterfly reduction across the warp
#pragma unroll
        for (int off = 16; off > 0; off >>= 1)
            s += __shfl_xor_sync(0xFFFFFFFFu, s, off);

        if (lane == 0)
            g_table[g * HIDDEN + c] = s + b[c];
    }
}

// ---------------------------------------------------------------------------
// Kernel 2: main.  Each block handles PPB=16 pairs; warp w owns pairs
// {w, w+4, w+8, w+12} (block-local).
//   Phase 1 (warp-local, no barriers): lanes 0..3 compute (gi, frac) for the
//     warp's 4 pairs (1 atan2 per pair); broadcast via shfl.
//   Phase 2 (batched): issue all 8 table loads (MLP=8, L1-hot), then 4x
//     lerp + streaming STG.128 back-to-back so the store stream never stalls
//     behind L1 latency.  launch_bounds(128,8) caps regs at 64 so ptxas can
//     keep all 8 float4 values live.
// ---------------------------------------------------------------------------
__global__ __launch_bounds__(HIDDEN, 8) void geom_embed_kernel(
    const float* __restrict__ normals,  // [1024][3]
    float*       __restrict__ out)      // [1024*1024][128]
{
    const int  tid   = threadIdx.x;
    const int  warp  = tid >> 5;
    const int  lane  = tid & 31;
    const long pbase = (long)blockIdx.x * PPB;

    // Phase 1: lanes 0..3 each handle one of this warp's pairs.
    int   gi_r = 0;
    float f_r  = 0.0f;
    if (lane < 4) {
        const int p = (int)pbase + warp + lane * 4;
        const int i = p >> 10;
        const int j = p & (NPTS - 1);

        const float ax = normals[i * 3 + 0];
        const float ay = normals[i * 3 + 1];
        const float az = normals[i * 3 + 2];
        const float bx = normals[j * 3 + 0];
        const float by = normals[j * 3 + 1];
        const float bz = normals[j * 3 + 2];

        const float cx = ay * bz - az * by;
        const float cy = az * bx - ax * bz;
        const float cz = ax * by - ay * bx;

        const float sv  = sqrtf(cx * cx + cy * cy + cz * cz);
        const float cv  = ax * bx + ay * by + az * bz;
        const float ang = atan2f(sv, cv);            // in [0, pi]

        // u = a * (G-1)/12 = ang * (G-1)/pi
        float u = ang * ((float)(G_TAB - 1) / PI_F);
        u = fminf(fmaxf(u, 0.0f), (float)(G_TAB - 1));
        int gi = (int)u;
        if (gi > G_TAB - 2) gi = G_TAB - 2;
        gi_r = gi;
        f_r  = u - (float)gi;
    }

    // Broadcast all 4 pair params up front.
    int   gi[4];
    float f[4];
#pragma unroll
    for (int it = 0; it < 4; ++it) {
        gi[it] = __shfl_sync(0xFFFFFFFFu, gi_r, it);
        f[it]  = __shfl_sync(0xFFFFFFFFu, f_r,  it);
    }

    const float4* __restrict__ T4 = (const float4*)g_table;   // 32 float4 per row
    float4* __restrict__ out4     = (float4*)out;

    // Batched loads: 8 independent L1 accesses in flight.
    float4 c0[4], c1[4];
#pragma unroll
    for (int it = 0; it < 4; ++it) {
        c0[it] = T4[gi[it] * 32 + lane];
        c1[it] = T4[gi[it] * 32 + 32 + lane];
    }

    // Lerp + streaming stores back-to-back.
#pragma unroll
    for (int it = 0; it < 4; ++it) {
        float4 r;
        r.x = fmaf(f[it], c1[it].x - c0[it].x, c0[it].x);
        r.y = fmaf(f[it], c1[it].y - c0[it].y, c0[it].y);
        r.z = fmaf(f[it], c1[it].z - c0[it].z, c0[it].z);
        r.w = fmaf(f[it], c1[it].w - c0[it].w, c0[it].w);

        __stcs(&out4[(pbase + warp + it * 4) * 32 + lane], r);
    }
}

// ---------------------------------------------------------------------------
// Launch.  Inputs (metadata order): points[unused], normals, W, b.
// ---------------------------------------------------------------------------
extern "C" void kernel_launch(void* const* d_in, const int* in_sizes, int n_in,
                              void* d_out, int out_size)
{
    const float* normals = (const float*)d_in[1];
    const float* W       = (const float*)d_in[2];
    const float* b       = (const float*)d_in[3];
    float* out           = (float*)d_out;

    build_table_kernel<<<G_TAB, HIDDEN>>>(W, b);
    geom_embed_kernel<<<NPAIRS / PPB, HIDDEN>>>(normals, out);
}